// round 14
// baseline (speedup 1.0000x reference)
#include <cuda_runtime.h>
#include <cuda_bf16.h>

constexpr int Bn  = 4096;
constexpr int Tn  = 4096;
constexpr int NC  = 256;          // chunks per row
constexpr int Tc  = Tn / NC;      // 16 steps per chunk
constexpr int SL  = 16;           // steps per slice (== chunk)
constexpr int RPB = 128;          // rows per block (= threads per block)
constexpr int PAD = 130;          // smem row stride in words
constexpr int NRG = Bn / RPB;     // 32 row-groups

__device__ float4 d_ALH[NC * Bn]; // chunk aggregate: (shift, lo, hi, unused)
__device__ float  d_S[NC * Bn];   // chunk END state (inclusive)
__device__ int    d_flag[NC * NRG];// 0 none, 1 aggregate, 2 inclusive

// step map as clamp: s -> min(max(s + a, L), H)
__device__ __forceinline__ void compose_step(
    float ga, float pa, float pp, float& A, float& L, float& H)
{
    const float K  = 5.0f / 60.0f;
    const float RK = 5.0f * K;

    float p   = fminf(fmaxf(pa * pp, 0.0f), 5.0f) * K;
    float glK = fmaxf(ga * 5.0f, -5.0f) * K;
    float a   = fminf(p + glK, RK);
    float h   = 13.5f + fminf(glK, 0.0f);

    A = A + a;
    L = fmaxf(L + a, 0.0f);
    H = fminf(fmaxf(H + a, 0.0f), h);
}

// returns new state; cost_raw = grid_amt + pv_export (price applied at flush)
__device__ __forceinline__ float battery_step(
    float s, float ga, float pa, float pp,
    float& cost_raw, float& trace_out)
{
    const float C = 13.5f;
    const float K = 5.0f / 60.0f;
    const float R = 5.0f;

    float rp  = fminf(fmaxf(pa * pp, 0.0f), R);
    float p   = rp * K;
    float gl  = fmaxf(ga * R, -R);
    float pvk = pp * K;

    float after_pv = fminf(s + p, C);
    float amt      = after_pv - s;
    float hi       = R - amt * 12.0f;
    float rgr      = fminf(gl, hi);
    float ns       = fminf(fmaxf(after_pv + rgr * K, 0.0f), C);

    float grid_amt  = ns - after_pv;
    float pv_export = amt - pvk;
    cost_raw  = grid_amt + pv_export;
    trace_out = ns;
    return ns;
}

// stage one array's [128 rows x 64B] chunk into time-major smem [SL][PAD]
__device__ __forceinline__ void stage_chunk(
    const float* __restrict__ g, size_t chunk_base, int tq, int rophase,
    float* __restrict__ sm)
{
#pragma unroll
    for (int p = 0; p < 4; ++p) {
        const int row = p * 32 + rophase;
        const float4 v = __ldcs(reinterpret_cast<const float4*>(
            g + chunk_base + (size_t)row * Tn + tq * 4));
        sm[(tq * 4 + 0) * PAD + row] = v.x;
        sm[(tq * 4 + 1) * PAD + row] = v.y;
        sm[(tq * 4 + 2) * PAD + row] = v.z;
        sm[(tq * 4 + 3) * PAD + row] = v.w;
    }
}

__global__ void __launch_bounds__(256) reset_flags_kernel()
{
    const int i = blockIdx.x * 256 + threadIdx.x;
    if (i < NC * NRG) d_flag[i] = 0;
}

__global__ void __launch_bounds__(RPB, 8) fused_kernel(
    const float* __restrict__ g_ga, const float* __restrict__ g_pa,
    const float* __restrict__ g_pp, const float* __restrict__ g_pr,
    float* __restrict__ g_trace, float* __restrict__ g_cost)
{
    __shared__ float sGA[SL * PAD], sPA[SL * PAD], sPP[SL * PAD];
    __shared__ int s_wd, s_wt;

    const int t  = threadIdx.x;
    const int rg = blockIdx.x & (NRG - 1);
    const int c  = blockIdx.x >> 5;
    const int b0 = rg * RPB;
    const int b  = b0 + t;

    const int tq      = t & 3;
    const int rophase = t >> 2;
    const int w       = t >> 5;
    const int lane    = t & 31;
    const int l16     = lane & 15;
    const int rh      = lane >> 4;

    const size_t base = (size_t)b0 * Tn + (size_t)c * Tc;

    // ── Stage ga/pa/pp and compose chunk clamp function ─────────────────
    stage_chunk(g_ga, base, tq, rophase, sGA);
    stage_chunk(g_pa, base, tq, rophase, sPA);
    stage_chunk(g_pp, base, tq, rophase, sPP);
    __syncthreads();

    float A = 0.0f, L = 0.0f, H = 13.5f;   // identity on [0, C]
#pragma unroll
    for (int tt = 0; tt < SL; ++tt)
        compose_step(sGA[tt * PAD + t], sPA[tt * PAD + t],
                     sPP[tt * PAD + t], A, L, H);

    d_ALH[(size_t)c * Bn + b] = make_float4(A, L, H, 0.0f);
    __threadfence();
    __syncthreads();
    if (t == 0) atomicExch(&d_flag[c * NRG + rg], 1);

    // ── Windowed warp-parallel lookback ─────────────────────────────────
    float s0 = 6.75f;
    if (c != 0) {
        float aA = 0.0f, aL = -3.4e38f, aH = 3.4e38f;   // identity
        int cc = c;
        for (;;) {
            __syncthreads();
            if (w == 0) {
                int wd = 0, wt = 2;
                for (;;) {
                    const int p = cc - 1 - lane;
                    int v = 2;
                    if (p >= 0) v = __ldcg(&d_flag[p * NRG + rg]);
                    const unsigned m2 = __ballot_sync(0xffffffffu, v == 2);
                    const unsigned m1 = __ballot_sync(0xffffffffu, v >= 1);
                    if (m2) {
                        const int l2 = __ffs(m2) - 1;
                        const unsigned need = (l2 == 0) ? 0u : ((1u << l2) - 1u);
                        if ((m1 & need) == need) {
                            wd = l2;
                            wt = (cc - 1 - l2 < 0) ? 1 : 0;  // 1 = hit initial state
                            break;
                        }
                    } else if (m1 == 0xffffffffu) {
                        wd = 32; wt = 2;                     // slide window deeper
                        break;
                    }
                    __nanosleep(50);
                }
                if (lane == 0) { s_wd = wd; s_wt = wt; }
            }
            __syncthreads();
            const int wd = s_wd;
            const int wt = s_wt;

            // every thread composes its own row's aggregates, newest first.
            // 4-wide load batches: independent LDGs issued together, composed
            // strictly in order (associativity => bit-identical).
            const float4* src = &d_ALH[(size_t)(cc - 1) * Bn + b];
            int l = 0;
            for (; l + 4 <= wd; l += 4) {
                const float4 f0 = __ldcg(src - (size_t)(l + 0) * Bn);
                const float4 f1 = __ldcg(src - (size_t)(l + 1) * Bn);
                const float4 f2 = __ldcg(src - (size_t)(l + 2) * Bn);
                const float4 f3 = __ldcg(src - (size_t)(l + 3) * Bn);
                float nl, nh;
                nl = fmaxf(f0.y + aA, aL); nh = fminf(fmaxf(f0.z + aA, aL), aH);
                aA += f0.x; aL = nl; aH = nh;
                nl = fmaxf(f1.y + aA, aL); nh = fminf(fmaxf(f1.z + aA, aL), aH);
                aA += f1.x; aL = nl; aH = nh;
                nl = fmaxf(f2.y + aA, aL); nh = fminf(fmaxf(f2.z + aA, aL), aH);
                aA += f2.x; aL = nl; aH = nh;
                nl = fmaxf(f3.y + aA, aL); nh = fminf(fmaxf(f3.z + aA, aL), aH);
                aA += f3.x; aL = nl; aH = nh;
            }
            for (; l < wd; ++l) {
                const float4 f = __ldcg(src - (size_t)l * Bn);
                const float nl = fmaxf(f.y + aA, aL);
                const float nh = fminf(fmaxf(f.z + aA, aL), aH);
                aA += f.x; aL = nl; aH = nh;
            }
            if (wt == 0) {
                const float sp = __ldcg(&d_S[(size_t)(cc - 1 - wd) * Bn + b]);
                s0 = fminf(fmaxf(sp + aA, aL), aH);
                break;
            }
            if (wt == 1) {
                s0 = fminf(fmaxf(6.75f + aA, aL), aH);
                break;
            }
            cc -= 32;
        }
    }

    // publish inclusive end-state of this chunk
    d_S[(size_t)c * Bn + b] = fminf(fmaxf(s0 + A, L), H);
    __threadfence();
    __syncthreads();
    if (t == 0) atomicExch(&d_flag[c * NRG + rg], 2);

    // ── Replay chunk from smem (no DRAM re-read) ────────────────────────
    float s = s0;
    if (c == 0) g_trace[(size_t)b * (Tn + 1)] = 6.75f;

#pragma unroll
    for (int tt = 0; tt < SL; ++tt) {
        float craw, tr;
        s = battery_step(s, sGA[tt * PAD + t], sPA[tt * PAD + t],
                         sPP[tt * PAD + t], craw, tr);
        sGA[tt * PAD + t] = tr;      // trace in place
        sPP[tt * PAD + t] = craw;    // unscaled cost in place
    }
    __syncthreads();

    // ── Flush: coalesced streaming stores; price applied here ───────────
    const int tcol = c * Tc;
#pragma unroll
    for (int rr = 0; rr < 32; rr += 2) {
        const int r = w * 32 + rr + rh;
        const float trv = sGA[l16 * PAD + r];
        const float craw = sPP[l16 * PAD + r];
        const float prv = __ldcs(&g_pr[(size_t)(b0 + r) * Tn + tcol + l16]);
        const float cov = (prv * 1.0e-3f) * craw;
        __stcs(&g_trace[(size_t)(b0 + r) * (Tn + 1) + tcol + 1 + l16], trv);
        __stcs(&g_cost [(size_t)(b0 + r) * Tn       + tcol + l16],     cov);
    }
}

extern "C" void kernel_launch(void* const* d_in, const int* in_sizes, int n_in,
                              void* d_out, int out_size)
{
    const float* ga = (const float*)d_in[0];
    const float* pa = (const float*)d_in[1];
    const float* pp = (const float*)d_in[2];
    const float* pr = (const float*)d_in[3];

    float* out   = (float*)d_out;
    float* trace = out;                               // [B, T+1]
    float* cost  = out + (size_t)Bn * (Tn + 1);       // [B, T]

    reset_flags_kernel<<<(NC * NRG + 255) / 256, 256>>>();
    fused_kernel<<<NC * NRG, RPB>>>(ga, pa, pp, pr, trace, cost);
}

// round 15
// speedup vs baseline: 1.4167x; 1.4167x over previous
#include <cuda_runtime.h>
#include <cuda_bf16.h>

constexpr int Bn  = 4096;
constexpr int Tn  = 4096;
constexpr int NC  = 256;          // chunks per row
constexpr int Tc  = Tn / NC;      // 16 steps per chunk
constexpr int SL  = 16;           // steps per slice (== chunk)
constexpr int RPB = 128;          // rows per block (= threads per block)
constexpr int PAD = 130;          // smem row stride in words
constexpr int NRG = Bn / RPB;     // 32 row-groups

__device__ float4 d_ALH[NC * Bn]; // chunk aggregate: (shift, lo, hi, unused)
__device__ float  d_S[NC * Bn];   // chunk END state (inclusive)
__device__ int    d_flag[NC * NRG];// 0 none, 1 aggregate, 2 inclusive

// step map as clamp: s -> min(max(s + a, L), H)
__device__ __forceinline__ void compose_step(
    float ga, float pa, float pp, float& A, float& L, float& H)
{
    const float K  = 5.0f / 60.0f;
    const float RK = 5.0f * K;

    float p   = fminf(fmaxf(pa * pp, 0.0f), 5.0f) * K;
    float glK = fmaxf(ga * 5.0f, -5.0f) * K;
    float a   = fminf(p + glK, RK);
    float h   = 13.5f + fminf(glK, 0.0f);

    A = A + a;
    L = fmaxf(L + a, 0.0f);
    H = fminf(fmaxf(H + a, 0.0f), h);
}

__device__ __forceinline__ float battery_step(
    float s, float ga, float pa, float pp, float pr,
    float& cost_out, float& trace_out)
{
    const float C = 13.5f;
    const float K = 5.0f / 60.0f;
    const float R = 5.0f;

    float rp  = fminf(fmaxf(pa * pp, 0.0f), R);
    float p   = rp * K;
    float gl  = fmaxf(ga * R, -R);
    float pvk = pp * K;
    float prc = pr * 1.0e-3f;

    float after_pv = fminf(s + p, C);
    float amt      = after_pv - s;
    float hi       = R - amt * 12.0f;
    float rgr      = fminf(gl, hi);
    float ns       = fminf(fmaxf(after_pv + rgr * K, 0.0f), C);

    float grid_amt  = ns - after_pv;
    float pv_export = amt - pvk;
    cost_out  = prc * (grid_amt + pv_export);
    trace_out = ns;
    return ns;
}

// stage one array's [128 rows x 64B] chunk into time-major smem [SL][PAD]
__device__ __forceinline__ void stage_chunk(
    const float* __restrict__ g, size_t chunk_base, int tq, int rophase,
    float* __restrict__ sm)
{
#pragma unroll
    for (int p = 0; p < 4; ++p) {
        const int row = p * 32 + rophase;
        const float4 v = __ldcs(reinterpret_cast<const float4*>(
            g + chunk_base + (size_t)row * Tn + tq * 4));
        sm[(tq * 4 + 0) * PAD + row] = v.x;
        sm[(tq * 4 + 1) * PAD + row] = v.y;
        sm[(tq * 4 + 2) * PAD + row] = v.z;
        sm[(tq * 4 + 3) * PAD + row] = v.w;
    }
}

__global__ void __launch_bounds__(256) reset_flags_kernel()
{
    const int i = blockIdx.x * 256 + threadIdx.x;
    if (i < NC * NRG) d_flag[i] = 0;
}

__global__ void __launch_bounds__(RPB, 6) fused_kernel(
    const float* __restrict__ g_ga, const float* __restrict__ g_pa,
    const float* __restrict__ g_pp, const float* __restrict__ g_pr,
    float* __restrict__ g_trace, float* __restrict__ g_cost)
{
    __shared__ float sGA[SL * PAD], sPA[SL * PAD], sPP[SL * PAD], sPR[SL * PAD];
    __shared__ int s_wd, s_wt;

    const int t  = threadIdx.x;
    const int rg = blockIdx.x & (NRG - 1);
    const int c  = blockIdx.x >> 5;
    const int b0 = rg * RPB;
    const int b  = b0 + t;

    const int tq      = t & 3;
    const int rophase = t >> 2;
    const int w       = t >> 5;
    const int lane    = t & 31;
    const int l16     = lane & 15;
    const int rh      = lane >> 4;

    const size_t base = (size_t)b0 * Tn + (size_t)c * Tc;

    // ── Issue price loads early; scatter later (hidden under lookback) ──
    float4 vpr[4];
#pragma unroll
    for (int p = 0; p < 4; ++p) {
        const int row = p * 32 + rophase;
        vpr[p] = __ldcs(reinterpret_cast<const float4*>(
            g_pr + base + (size_t)row * Tn + tq * 4));
    }

    // ── Stage ga/pa/pp and compose chunk clamp function ─────────────────
    stage_chunk(g_ga, base, tq, rophase, sGA);
    stage_chunk(g_pa, base, tq, rophase, sPA);
    stage_chunk(g_pp, base, tq, rophase, sPP);
    __syncthreads();

    float A = 0.0f, L = 0.0f, H = 13.5f;   // identity on [0, C]
#pragma unroll
    for (int tt = 0; tt < SL; ++tt)
        compose_step(sGA[tt * PAD + t], sPA[tt * PAD + t],
                     sPP[tt * PAD + t], A, L, H);

    d_ALH[(size_t)c * Bn + b] = make_float4(A, L, H, 0.0f);
    __threadfence();
    __syncthreads();
    if (t == 0) atomicExch(&d_flag[c * NRG + rg], 1);

    // ── Windowed warp-parallel lookback ─────────────────────────────────
    float s0 = 6.75f;
    if (c != 0) {
        float aA = 0.0f, aL = -3.4e38f, aH = 3.4e38f;   // identity
        int cc = c;
        for (;;) {
            __syncthreads();
            if (w == 0) {
                int wd = 0, wt = 2;
                for (;;) {
                    const int p = cc - 1 - lane;
                    int v = 2;
                    if (p >= 0) v = __ldcg(&d_flag[p * NRG + rg]);
                    const unsigned m2 = __ballot_sync(0xffffffffu, v == 2);
                    const unsigned m1 = __ballot_sync(0xffffffffu, v >= 1);
                    if (m2) {
                        const int l2 = __ffs(m2) - 1;
                        const unsigned need = (l2 == 0) ? 0u : ((1u << l2) - 1u);
                        if ((m1 & need) == need) {
                            wd = l2;
                            wt = (cc - 1 - l2 < 0) ? 1 : 0;  // 1 = hit initial state
                            break;
                        }
                    } else if (m1 == 0xffffffffu) {
                        wd = 32; wt = 2;                     // slide window deeper
                        break;
                    }
                    __nanosleep(50);
                }
                if (lane == 0) { s_wd = wd; s_wt = wt; }
            }
            __syncthreads();
            const int wd = s_wd;
            const int wt = s_wt;

            // every thread composes its own row's aggregates, newest first.
            // 4-wide load batches: independent LDGs issued together, composed
            // strictly in order (associativity => bit-identical).
            const float4* src = &d_ALH[(size_t)(cc - 1) * Bn + b];
            int l = 0;
            for (; l + 4 <= wd; l += 4) {
                const float4 f0 = __ldcg(src - (size_t)(l + 0) * Bn);
                const float4 f1 = __ldcg(src - (size_t)(l + 1) * Bn);
                const float4 f2 = __ldcg(src - (size_t)(l + 2) * Bn);
                const float4 f3 = __ldcg(src - (size_t)(l + 3) * Bn);
                float nl, nh;
                nl = fmaxf(f0.y + aA, aL); nh = fminf(fmaxf(f0.z + aA, aL), aH);
                aA += f0.x; aL = nl; aH = nh;
                nl = fmaxf(f1.y + aA, aL); nh = fminf(fmaxf(f1.z + aA, aL), aH);
                aA += f1.x; aL = nl; aH = nh;
                nl = fmaxf(f2.y + aA, aL); nh = fminf(fmaxf(f2.z + aA, aL), aH);
                aA += f2.x; aL = nl; aH = nh;
                nl = fmaxf(f3.y + aA, aL); nh = fminf(fmaxf(f3.z + aA, aL), aH);
                aA += f3.x; aL = nl; aH = nh;
            }
            for (; l < wd; ++l) {
                const float4 f = __ldcg(src - (size_t)l * Bn);
                const float nl = fmaxf(f.y + aA, aL);
                const float nh = fminf(fmaxf(f.z + aA, aL), aH);
                aA += f.x; aL = nl; aH = nh;
            }
            if (wt == 0) {
                const float sp = __ldcg(&d_S[(size_t)(cc - 1 - wd) * Bn + b]);
                s0 = fminf(fmaxf(sp + aA, aL), aH);
                break;
            }
            if (wt == 1) {
                s0 = fminf(fmaxf(6.75f + aA, aL), aH);
                break;
            }
            cc -= 32;
        }
    }

    // scatter prefetched price tile (latency already hidden)
#pragma unroll
    for (int p = 0; p < 4; ++p) {
        const int row = p * 32 + rophase;
        sPR[(tq * 4 + 0) * PAD + row] = vpr[p].x;
        sPR[(tq * 4 + 1) * PAD + row] = vpr[p].y;
        sPR[(tq * 4 + 2) * PAD + row] = vpr[p].z;
        sPR[(tq * 4 + 3) * PAD + row] = vpr[p].w;
    }

    // publish inclusive end-state of this chunk
    d_S[(size_t)c * Bn + b] = fminf(fmaxf(s0 + A, L), H);
    __threadfence();
    __syncthreads();
    if (t == 0) atomicExch(&d_flag[c * NRG + rg], 2);

    // ── Replay chunk from smem (no DRAM re-read) ────────────────────────
    float s = s0;
    if (c == 0) g_trace[(size_t)b * (Tn + 1)] = 6.75f;

#pragma unroll
    for (int tt = 0; tt < SL; ++tt) {
        float cost, tr;
        s = battery_step(s, sGA[tt * PAD + t], sPA[tt * PAD + t],
                         sPP[tt * PAD + t], sPR[tt * PAD + t], cost, tr);
        sGA[tt * PAD + t] = tr;      // trace in place
        sPR[tt * PAD + t] = cost;    // cost in place
    }
    __syncthreads();

    // ── Flush: coalesced streaming stores, 2 rows per iteration ─────────
    const int tcol = c * Tc;
#pragma unroll
    for (int rr = 0; rr < 32; rr += 2) {
        const int r = w * 32 + rr + rh;
        const float trv = sGA[l16 * PAD + r];
        const float cov = sPR[l16 * PAD + r];
        __stcs(&g_trace[(size_t)(b0 + r) * (Tn + 1) + tcol + 1 + l16], trv);
        __stcs(&g_cost [(size_t)(b0 + r) * Tn       + tcol + l16],     cov);
    }
}

extern "C" void kernel_launch(void* const* d_in, const int* in_sizes, int n_in,
                              void* d_out, int out_size)
{
    const float* ga = (const float*)d_in[0];
    const float* pa = (const float*)d_in[1];
    const float* pp = (const float*)d_in[2];
    const float* pr = (const float*)d_in[3];

    float* out   = (float*)d_out;
    float* trace = out;                               // [B, T+1]
    float* cost  = out + (size_t)Bn * (Tn + 1);       // [B, T]

    reset_flags_kernel<<<(NC * NRG + 255) / 256, 256>>>();
    fused_kernel<<<NC * NRG, RPB>>>(ga, pa, pp, pr, trace, cost);
}

// round 16
// speedup vs baseline: 1.5668x; 1.1059x over previous
#include <cuda_runtime.h>
#include <cuda_bf16.h>

constexpr int Bn  = 4096;
constexpr int Tn  = 4096;
constexpr int NC  = 256;          // chunks per row
constexpr int Tc  = Tn / NC;      // 16 steps per chunk
constexpr int SL  = 16;           // steps per slice (== chunk)
constexpr int RPB = 128;          // rows per block (= threads per block)
constexpr int PAD = 130;          // smem row stride in words
constexpr int NRG = Bn / RPB;     // 32 row-groups

__device__ float4 d_ALH[NC * Bn]; // chunk aggregate: (shift, lo, hi, unused)
__device__ float  d_S[NC * Bn];   // chunk END state (inclusive)
__device__ int    d_flag[NC * NRG];// 0 none, 1 aggregate, 2 inclusive

__global__ void __launch_bounds__(256) reset_flags_kernel()
{
    const int i = blockIdx.x * 256 + threadIdx.x;
    if (i < NC * NRG) d_flag[i] = 0;
}

__global__ void __launch_bounds__(RPB, 8) fused_kernel(
    const float* __restrict__ g_ga, const float* __restrict__ g_pa,
    const float* __restrict__ g_pp, const float* __restrict__ g_pr,
    float* __restrict__ g_trace, float* __restrict__ g_cost)
{
    // 3 time-major tiles: p, glK, pvk  (trace/cost written in place later)
    __shared__ float sP[SL * PAD], sG[SL * PAD], sV[SL * PAD];
    __shared__ int s_wd, s_wt;

    const float C  = 13.5f;
    const float K  = 5.0f / 60.0f;
    const float RK = 5.0f * K;

    const int t  = threadIdx.x;
    const int rg = blockIdx.x & (NRG - 1);
    const int c  = blockIdx.x >> 5;
    const int b0 = rg * RPB;
    const int b  = b0 + t;

    const int tq      = t & 3;
    const int rophase = t >> 2;
    const int w       = t >> 5;
    const int lane    = t & 31;
    const int l16     = lane & 15;
    const int rh      = lane >> 4;

    const int    tcol = c * Tc;
    const size_t base = (size_t)b0 * Tn + (size_t)tcol;

    // ── Price prefetch in the FLUSH access pattern (independent LDG.32) ─
    // Row for flush iteration i: w*32 + 2*i + rh, column tcol + l16.
    float prv[16];
#pragma unroll
    for (int i = 0; i < 16; ++i) {
        const int r = w * 32 + 2 * i + rh;
        prv[i] = __ldcs(&g_pr[(size_t)(b0 + r) * Tn + tcol + l16]);
    }

    // ── Stage: load ga/pa/pp, compute derived (p, glK, pvk), scatter ────
#pragma unroll
    for (int pp4 = 0; pp4 < 4; ++pp4) {
        const int row = pp4 * 32 + rophase;
        const size_t off = base + (size_t)row * Tn + tq * 4;
        const float4 vga = __ldcs(reinterpret_cast<const float4*>(g_ga + off));
        const float4 vpa = __ldcs(reinterpret_cast<const float4*>(g_pa + off));
        const float4 vpp = __ldcs(reinterpret_cast<const float4*>(g_pp + off));

        const float ga[4] = {vga.x, vga.y, vga.z, vga.w};
        const float pa[4] = {vpa.x, vpa.y, vpa.z, vpa.w};
        const float pv[4] = {vpp.x, vpp.y, vpp.z, vpp.w};
#pragma unroll
        for (int k = 0; k < 4; ++k) {
            const float pk   = fminf(fmaxf(pa[k] * pv[k], 0.0f), 5.0f) * K;
            const float glKk = fmaxf(ga[k] * 5.0f, -5.0f) * K;
            const float pvkk = pv[k] * K;
            const int tt = tq * 4 + k;
            sP[tt * PAD + row] = pk;
            sG[tt * PAD + row] = glKk;
            sV[tt * PAD + row] = pvkk;
        }
    }
    __syncthreads();

    // ── Compose chunk clamp function from smem ──────────────────────────
    float A = 0.0f, L = 0.0f, H = 13.5f;   // identity on [0, C]
#pragma unroll
    for (int tt = 0; tt < SL; ++tt) {
        const float p   = sP[tt * PAD + t];
        const float glK = sG[tt * PAD + t];
        const float a   = fminf(p + glK, RK);
        const float h   = 13.5f + fminf(glK, 0.0f);
        A = A + a;
        L = fmaxf(L + a, 0.0f);
        H = fminf(fmaxf(H + a, 0.0f), h);
    }

    d_ALH[(size_t)c * Bn + b] = make_float4(A, L, H, 0.0f);
    __threadfence();
    __syncthreads();
    if (t == 0) atomicExch(&d_flag[c * NRG + rg], 1);

    // ── Windowed warp-parallel lookback (simple serial compose) ─────────
    float s0 = 6.75f;
    if (c != 0) {
        float aA = 0.0f, aL = -3.4e38f, aH = 3.4e38f;   // identity
        int cc = c;
        for (;;) {
            __syncthreads();
            if (w == 0) {
                int wd = 0, wt = 2;
                for (;;) {
                    const int p = cc - 1 - lane;
                    int v = 2;
                    if (p >= 0) v = __ldcg(&d_flag[p * NRG + rg]);
                    const unsigned m2 = __ballot_sync(0xffffffffu, v == 2);
                    const unsigned m1 = __ballot_sync(0xffffffffu, v >= 1);
                    if (m2) {
                        const int l2 = __ffs(m2) - 1;
                        const unsigned need = (l2 == 0) ? 0u : ((1u << l2) - 1u);
                        if ((m1 & need) == need) {
                            wd = l2;
                            wt = (cc - 1 - l2 < 0) ? 1 : 0;  // 1 = hit initial state
                            break;
                        }
                    } else if (m1 == 0xffffffffu) {
                        wd = 32; wt = 2;                     // slide window deeper
                        break;
                    }
                    __nanosleep(50);
                }
                if (lane == 0) { s_wd = wd; s_wt = wt; }
            }
            __syncthreads();
            const int wd = s_wd;
            const int wt = s_wt;

            // each thread composes its own row's aggregates, newest first
            for (int l = 0; l < wd; ++l) {
                const float4 f = __ldcg(&d_ALH[(size_t)(cc - 1 - l) * Bn + b]);
                const float nl = fmaxf(f.y + aA, aL);        // acc ∘ F_p
                const float nh = fminf(fmaxf(f.z + aA, aL), aH);
                aA += f.x;
                aL = nl; aH = nh;
            }
            if (wt == 0) {
                const float sp = __ldcg(&d_S[(size_t)(cc - 1 - wd) * Bn + b]);
                s0 = fminf(fmaxf(sp + aA, aL), aH);
                break;
            }
            if (wt == 1) {
                s0 = fminf(fmaxf(6.75f + aA, aL), aH);
                break;
            }
            cc -= 32;
        }
    }

    // publish inclusive end-state of this chunk
    d_S[(size_t)c * Bn + b] = fminf(fmaxf(s0 + A, L), H);
    __threadfence();
    __syncthreads();
    if (t == 0) atomicExch(&d_flag[c * NRG + rg], 2);

    // ── Replay chunk from smem; trace/cost overwrite consumed tiles ─────
    float s = s0;
    if (c == 0) g_trace[(size_t)b * (Tn + 1)] = 6.75f;

#pragma unroll
    for (int tt = 0; tt < SL; ++tt) {
        const float p   = sP[tt * PAD + t];
        const float glK = sG[tt * PAD + t];
        const float pvk = sV[tt * PAD + t];

        const float after_pv = fminf(s + p, C);
        const float amt      = after_pv - s;
        const float hiK      = (5.0f - amt * 12.0f) * K;
        const float rgrK     = fminf(glK, hiK);
        const float ns       = fminf(fmaxf(after_pv + rgrK, 0.0f), C);
        const float craw     = (ns - after_pv) + (amt - pvk);

        sP[tt * PAD + t] = ns;     // trace in place
        sG[tt * PAD + t] = craw;   // unscaled cost in place
        s = ns;
    }
    __syncthreads();

    // ── Flush: coalesced streaming stores; price applied from registers ─
#pragma unroll
    for (int i = 0; i < 16; ++i) {
        const int r = w * 32 + 2 * i + rh;
        const float trv  = sP[l16 * PAD + r];
        const float craw = sG[l16 * PAD + r];
        const float cov  = (prv[i] * 1.0e-3f) * craw;
        __stcs(&g_trace[(size_t)(b0 + r) * (Tn + 1) + tcol + 1 + l16], trv);
        __stcs(&g_cost [(size_t)(b0 + r) * Tn       + tcol + l16],     cov);
    }
}

extern "C" void kernel_launch(void* const* d_in, const int* in_sizes, int n_in,
                              void* d_out, int out_size)
{
    const float* ga = (const float*)d_in[0];
    const float* pa = (const float*)d_in[1];
    const float* pp = (const float*)d_in[2];
    const float* pr = (const float*)d_in[3];

    float* out   = (float*)d_out;
    float* trace = out;                               // [B, T+1]
    float* cost  = out + (size_t)Bn * (Tn + 1);       // [B, T]

    reset_flags_kernel<<<(NC * NRG + 255) / 256, 256>>>();
    fused_kernel<<<NC * NRG, RPB>>>(ga, pa, pp, pr, trace, cost);
}